// round 16
// baseline (speedup 1.0000x reference)
#include <cuda_runtime.h>

#define B_   2
#define C_   128
#define HW   128
#define HD   64
#define L_   4096
#define NMAT 16777216u          // 4096*4096 = 2^24
#define SCALE_ 10.0f
#define TAU  1e-10f

// ---------------- scratch (static device globals; no runtime allocs) ----------------
__device__ float g_bufA[33554432];   // 2 * 4096 * 4096  (134 MB)
__device__ float g_bufB[33554432];   // 2 * 4096 * 4096  (134 MB)
__device__ float g_fd[B_ * C_ * L_]; // downsampled f  [b][c][i]
__device__ float g_bd[B_ * C_ * L_]; // downsampled b  [b][c][i]
__device__ float g_e[B_ * L_];       // per-pixel energy of b_ds
__device__ float g_norm[B_ * L_];    // patch rsqrt norms
__device__ float g_mm[L_];           // mask gate

// ---------------- zero output ----------------
__global__ void k_zero(float* __restrict__ out, int n) {
    int i = blockIdx.x * blockDim.x + threadIdx.x;
    if (i < n) out[i] = 0.0f;
}

// ---------------- downsample f,b (::2, ::2) into [b][c][i] layout ----------------
__global__ void k_prep_ds(const float* __restrict__ f, const float* __restrict__ b) {
    int n = blockIdx.x * blockDim.x + threadIdx.x;   // B_*C_*L_ = 1048576
    if (n >= B_ * C_ * L_) return;
    int i  = n & (L_ - 1);
    int bc = n >> 12;                 // b*128 + c
    int h = i >> 6, w = i & 63;
    size_t src = ((size_t)bc * HW + 2 * h) * HW + 2 * w;
    g_fd[n] = f[src];
    g_bd[n] = b[src];
}

// ---------------- per-pixel energy of b_ds ----------------
__global__ void k_energy() {
    int n = blockIdx.x * blockDim.x + threadIdx.x;   // B_*L_ = 8192
    if (n >= B_ * L_) return;
    int bb = n >> 12;
    int i  = n & (L_ - 1);
    const float* bd = g_bd + (size_t)bb * C_ * L_;
    float s = 0.0f;
#pragma unroll 8
    for (int c = 0; c < C_; c++) { float v = bd[c * L_ + i]; s += v * v; }
    g_e[n] = s;
}

// ---------------- patch norm: 3x3 box sum of energy (zero pad) + 0.1152, rsqrt ----------------
__global__ void k_norm() {
    int n = blockIdx.x * blockDim.x + threadIdx.x;
    if (n >= B_ * L_) return;
    int bb = n >> 12;
    int i  = n & (L_ - 1);
    int h = i >> 6, w = i & 63;
    const float* e = g_e + bb * L_;
    float s = 0.0f;
#pragma unroll
    for (int dh = -1; dh <= 1; dh++)
#pragma unroll
        for (int dw = -1; dw <= 1; dw++) {
            int hh = h + dh, ww = w + dw;
            if ((unsigned)hh < 64u && (unsigned)ww < 64u) s += e[hh * 64 + ww];
        }
    g_norm[n] = rsqrtf(s + 0.1152f);   // sum(w*w + 1e-4) over 128*3*3 elements
}

// ---------------- mask gate: mean of 3x3 patch of mask[::2,::2] == 0 ----------------
__global__ void k_mm(const float* __restrict__ mask) {
    int i = blockIdx.x * blockDim.x + threadIdx.x;
    if (i >= L_) return;
    int h = i >> 6, w = i & 63;
    float s = 0.0f;
#pragma unroll
    for (int dh = -1; dh <= 1; dh++)
#pragma unroll
        for (int dw = -1; dw <= 1; dw++) {
            int hh = h + dh, ww = w + dw;
            if ((unsigned)hh < 64u && (unsigned)ww < 64u)
                s += mask[(hh * 2) * HW + ww * 2];
        }
    g_mm[i] = ((s * (1.0f / 9.0f)) == 0.0f) ? 1.0f : 0.0f;
}

// ---------------- Gram GEMM: G[b][i][j] = sum_c bd[b][c][i] * fd[b][c][j] ----------------
// M=N=4096, K=128. 128x128 block tile, 256 threads, 8x8 micro-tile.
__global__ __launch_bounds__(256) void k_gemm() {
    int bb = blockIdx.z;
    int i0 = blockIdx.y * 128;
    int j0 = blockIdx.x * 128;
    const float* A  = g_bd + (size_t)bb * C_ * L_;   // [c][i]
    const float* Bm = g_fd + (size_t)bb * C_ * L_;   // [c][j]
    __shared__ float As[16][128];
    __shared__ float Bs[16][128];
    float acc[8][8];
#pragma unroll
    for (int u = 0; u < 8; u++)
#pragma unroll
        for (int v = 0; v < 8; v++) acc[u][v] = 0.0f;

    int tid = threadIdx.x;
    int tx = tid & 15, ty = tid >> 4;

    for (int k0 = 0; k0 < 128; k0 += 16) {
#pragma unroll
        for (int x = tid; x < 512; x += 256) {       // 16 rows * 32 float4
            int kk = x >> 5, c4 = (x & 31) << 2;
            *(float4*)&As[kk][c4] = *(const float4*)&A[(size_t)(k0 + kk) * L_ + i0 + c4];
            *(float4*)&Bs[kk][c4] = *(const float4*)&Bm[(size_t)(k0 + kk) * L_ + j0 + c4];
        }
        __syncthreads();
#pragma unroll
        for (int k = 0; k < 16; k++) {
            float4 a0 = *(float4*)&As[k][ty * 8];
            float4 a1 = *(float4*)&As[k][ty * 8 + 4];
            float4 b0 = *(float4*)&Bs[k][tx * 8];
            float4 b1 = *(float4*)&Bs[k][tx * 8 + 4];
            float av[8] = {a0.x, a0.y, a0.z, a0.w, a1.x, a1.y, a1.z, a1.w};
            float bv[8] = {b0.x, b0.y, b0.z, b0.w, b1.x, b1.y, b1.z, b1.w};
#pragma unroll
            for (int u = 0; u < 8; u++)
#pragma unroll
                for (int v = 0; v < 8; v++) acc[u][v] += av[u] * bv[v];
        }
        __syncthreads();
    }
    float* Cp = g_bufA + ((size_t)bb << 24);
#pragma unroll
    for (int u = 0; u < 8; u++) {
        size_t ro = (size_t)(i0 + ty * 8 + u) * L_ + j0 + tx * 8;
        *(float4*)&Cp[ro]     = make_float4(acc[u][0], acc[u][1], acc[u][2], acc[u][3]);
        *(float4*)&Cp[ro + 4] = make_float4(acc[u][4], acc[u][5], acc[u][6], acc[u][7]);
    }
}

// ---------------- diagonal patch box-sum, pass over dh (applied to hb AND hf) ----------------
__global__ void k_pass_dh() {
    size_t n = (size_t)blockIdx.x * blockDim.x + threadIdx.x;
    unsigned m = (unsigned)(n & (NMAT - 1));
    unsigned l = m >> 12, p = m & 4095;
    int hb = l >> 6, hf = p >> 6;
    const int OFF = 64 * 4096 + 64;     // +1 in hb and +1 in hf
    const float* in = g_bufA;
    float v = in[n];
    if (hb > 0  && hf > 0 ) v += in[n - OFF];
    if (hb < 63 && hf < 63) v += in[n + OFF];
    g_bufB[n] = v;
}

// ---------------- pass over dw (applied to wb AND wf), then * patch norm ----------------
__global__ void k_pass_dw() {
    size_t n = (size_t)blockIdx.x * blockDim.x + threadIdx.x;
    unsigned m = (unsigned)(n & (NMAT - 1));
    unsigned l = m >> 12, p = m & 4095;
    int wb = l & 63, wf = p & 63;
    const float* in = g_bufB;
    float v = in[n];
    if (wb > 0  && wf > 0 ) v += in[n - 4097];
    if (wb < 63 && wf < 63) v += in[n + 4097];
    g_bufA[n] = v * g_norm[(n >> 24) * L_ + l];
}

// ---------------- fuse #1: diagonal 3-tap in flattened (l, p) space ----------------
__global__ void k_fuse1() {
    size_t n = (size_t)blockIdx.x * blockDim.x + threadIdx.x;
    unsigned m = (unsigned)(n & (NMAT - 1));
    unsigned l = m >> 12, p = m & 4095;
    const float* in = g_bufA;
    float v = in[n];
    if (l > 0    && p > 0   ) v += in[n - 4097];
    if (l < 4095 && p < 4095) v += in[n + 4097];
    g_bufB[n] = v;
}

// ---------------- fuse #2 (transpose sandwich folded in) + mask gate, output TRANSPOSED [p][l] ----------------
__global__ void k_fuse2t() {
    int bz = blockIdx.z;
    int l0 = blockIdx.y << 5;
    int p0 = blockIdx.x << 5;
    __shared__ float s[32][33];
    int l = l0 + threadIdx.y;
    int p = p0 + threadIdx.x;
    int rt = ((l & 63) << 6) | (l >> 6);   // swap(l)
    int ct = ((p & 63) << 6) | (p >> 6);   // swap(p)
    const float* in = g_bufB + ((size_t)bz << 24);
    float v = 0.0f;
#pragma unroll
    for (int d = -1; d <= 1; d++) {
        int rr = rt + d, cc = ct + d;
        if ((unsigned)rr < 4096u && (unsigned)cc < 4096u) {
            int r2 = ((rr & 63) << 6) | (rr >> 6);
            int c2 = ((cc & 63) << 6) | (cc >> 6);
            v += in[((size_t)r2 << 12) + c2];
        }
    }
    s[threadIdx.y][threadIdx.x] = v * g_mm[l];
    __syncthreads();
    int po = p0 + threadIdx.y, lo = l0 + threadIdx.x;
    g_bufA[((size_t)bz << 24) + ((size_t)po << 12) + lo] = s[threadIdx.x][threadIdx.y];
}

// ---------------- softmax over l (contiguous rows of [b][p][l]), * mm after ----------------
__global__ void k_softmax() {
    int row = blockIdx.x;
    float* r = g_bufA + (size_t)row * L_;
    __shared__ float red[256];
    int tid = threadIdx.x;

    float m = -3.4e38f;
    for (int i = tid; i < L_; i += 256) m = fmaxf(m, r[i] * SCALE_);
    red[tid] = m; __syncthreads();
    for (int s = 128; s > 0; s >>= 1) { if (tid < s) red[tid] = fmaxf(red[tid], red[tid + s]); __syncthreads(); }
    m = red[0];
    __syncthreads();

    float sum = 0.0f;
    for (int i = tid; i < L_; i += 256) { float e = expf(r[i] * SCALE_ - m); r[i] = e; sum += e; }
    red[tid] = sum; __syncthreads();
    for (int s = 128; s > 0; s >>= 1) { if (tid < s) red[tid] += red[tid + s]; __syncthreads(); }
    float inv = 1.0f / red[0];

    for (int i = tid; i < L_; i += 256) r[i] = r[i] * inv * g_mm[i];
}

// ---------------- sparse transposed-conv paste ----------------
// out[c, 2*ih-1+kh, 2*iw-1+kw] += 0.25 * attn[l,(ih,iw)] * b[c, 2*hb-1+kh, 2*wb-1+kw]
// Weights <= TAU truncated (mass bound 4096*TAU = 4e-7, far below tolerance).
__global__ __launch_bounds__(512) void k_deconv(const float* __restrict__ bfull, float* __restrict__ out) {
    __shared__ int   s_idx[4096];
    __shared__ float s_w[4096];
    __shared__ int   s_cnt;
    int row = blockIdx.x;               // b*4096 + p
    int bb = row >> 12;
    int p  = row & 4095;
    int tid = threadIdx.x;
    if (tid == 0) s_cnt = 0;
    __syncthreads();

    const float* r = g_bufA + (size_t)row * L_;
    for (int i = tid; i < L_; i += 512) {
        float w = r[i];
        if (w > TAU) { int k = atomicAdd(&s_cnt, 1); s_idx[k] = i; s_w[k] = w; }
    }
    __syncthreads();
    int n = s_cnt;

    int ih = p >> 6, iw = p & 63;
    int c  = tid >> 2, kw = tid & 3;
    int ow = 2 * iw - 1 + kw;
    if ((unsigned)ow >= (unsigned)HW) return;

    float*       obase = out   + ((size_t)(bb * C_ + c) * HW) * HW + ow;
    const float* bbase = bfull + ((size_t)(bb * C_ + c) * HW) * HW;

    for (int s2 = 0; s2 < n; s2++) {
        int l = s_idx[s2];
        float w = 0.25f * s_w[s2];
        int hb = l >> 6, wb = l & 63;
        int bc = 2 * wb - 1 + kw;
        if ((unsigned)bc >= (unsigned)HW) continue;
        const float* bp = bbase + bc;
#pragma unroll
        for (int kh = 0; kh < 4; kh++) {
            int oh = 2 * ih - 1 + kh;
            int br = 2 * hb - 1 + kh;
            if ((unsigned)oh < (unsigned)HW && (unsigned)br < (unsigned)HW) {
                atomicAdd(obase + oh * HW, w * bp[br * HW]);
            }
        }
    }
}

// ---------------- launcher ----------------
extern "C" void kernel_launch(void* const* d_in, const int* in_sizes, int n_in,
                              void* d_out, int out_size) {
    (void)in_sizes; (void)n_in;
    const float* f    = (const float*)d_in[0];
    const float* b    = (const float*)d_in[1];
    const float* mask = (const float*)d_in[2];
    float* out = (float*)d_out;

    k_zero<<<(out_size + 255) / 256, 256>>>(out, out_size);
    k_prep_ds<<<(B_ * C_ * L_) / 256, 256>>>(f, b);
    k_energy<<<(B_ * L_) / 256, 256>>>();
    k_norm<<<(B_ * L_) / 256, 256>>>();
    k_mm<<<L_ / 256, 256>>>(mask);

    dim3 gg(32, 32, B_);
    k_gemm<<<gg, 256>>>();

    int pblocks = (int)(((size_t)B_ * NMAT) / 256);   // 131072
    k_pass_dh<<<pblocks, 256>>>();
    k_pass_dw<<<pblocks, 256>>>();
    k_fuse1<<<pblocks, 256>>>();

    dim3 gt(128, 128, B_), bt(32, 32);
    k_fuse2t<<<gt, bt>>>();

    k_softmax<<<B_ * L_, 256>>>();
    k_deconv<<<B_ * L_, 512>>>(b, out);
}

// round 17
// speedup vs baseline: 1.0664x; 1.0664x over previous
#include <cuda_runtime.h>

#define B_   2
#define C_   128
#define HW   128
#define L_   4096
#define NMAT 16777216u          // 4096*4096 = 2^24
#define SCALE_ 10.0f
#define TAU  1e-10f

typedef unsigned long long u64;

// ---------------- scratch (static device globals; no runtime allocs) ----------------
__device__ float g_bufA[33554432];   // 2 * 4096 * 4096  (134 MB)
__device__ float g_bufB[33554432];   // 2 * 4096 * 4096  (134 MB)
__device__ float g_fd[B_ * C_ * L_]; // downsampled f  [b][c][i]
__device__ float g_bd[B_ * C_ * L_]; // downsampled b  [b][c][i]
__device__ float g_e[B_ * L_];       // per-pixel energy of b_ds
__device__ float g_norm[B_ * L_];    // patch rsqrt norms
__device__ float g_mm[L_];           // mask gate
__device__ float g_max[B_ * L_];     // per-row max*SCALE
__device__ float g_inv[B_ * L_];     // per-row 1/sum(exp)

// ---------------- f32x2 packed math ----------------
__device__ __forceinline__ u64 pack_dup(float a) {
    u64 r;
    asm("mov.b64 %0, {%1, %1};" : "=l"(r) : "f"(a));
    return r;
}
__device__ __forceinline__ void ffma2(u64& d, u64 a, u64 b) {
    asm("fma.rn.f32x2 %0, %1, %2, %0;" : "+l"(d) : "l"(a), "l"(b));
}

// ---------------- zero output ----------------
__global__ void k_zero(float* __restrict__ out, int n) {
    int i = blockIdx.x * blockDim.x + threadIdx.x;
    if (i < n) out[i] = 0.0f;
}

// ---------------- downsample f,b (::2, ::2) into [b][c][i] layout ----------------
__global__ void k_prep_ds(const float* __restrict__ f, const float* __restrict__ b) {
    int n = blockIdx.x * blockDim.x + threadIdx.x;   // B_*C_*L_ = 1048576
    if (n >= B_ * C_ * L_) return;
    int i  = n & (L_ - 1);
    int bc = n >> 12;                 // b*128 + c
    int h = i >> 6, w = i & 63;
    size_t src = ((size_t)bc * HW + 2 * h) * HW + 2 * w;
    g_fd[n] = f[src];
    g_bd[n] = b[src];
}

// ---------------- per-pixel energy of b_ds ----------------
__global__ void k_energy() {
    int n = blockIdx.x * blockDim.x + threadIdx.x;   // B_*L_ = 8192
    if (n >= B_ * L_) return;
    int bb = n >> 12;
    int i  = n & (L_ - 1);
    const float* bd = g_bd + (size_t)bb * C_ * L_;
    float s = 0.0f;
#pragma unroll 8
    for (int c = 0; c < C_; c++) { float v = bd[c * L_ + i]; s += v * v; }
    g_e[n] = s;
}

// ---------------- patch norm: 3x3 box sum of energy (zero pad) + 0.1152, rsqrt ----------------
__global__ void k_norm() {
    int n = blockIdx.x * blockDim.x + threadIdx.x;
    if (n >= B_ * L_) return;
    int bb = n >> 12;
    int i  = n & (L_ - 1);
    int h = i >> 6, w = i & 63;
    const float* e = g_e + bb * L_;
    float s = 0.0f;
#pragma unroll
    for (int dh = -1; dh <= 1; dh++)
#pragma unroll
        for (int dw = -1; dw <= 1; dw++) {
            int hh = h + dh, ww = w + dw;
            if ((unsigned)hh < 64u && (unsigned)ww < 64u) s += e[hh * 64 + ww];
        }
    g_norm[n] = rsqrtf(s + 0.1152f);   // sum(w*w + 1e-4) over 128*3*3 slots
}

// ---------------- mask gate ----------------
__global__ void k_mm(const float* __restrict__ mask) {
    int i = blockIdx.x * blockDim.x + threadIdx.x;
    if (i >= L_) return;
    int h = i >> 6, w = i & 63;
    float s = 0.0f;
#pragma unroll
    for (int dh = -1; dh <= 1; dh++)
#pragma unroll
        for (int dw = -1; dw <= 1; dw++) {
            int hh = h + dh, ww = w + dw;
            if ((unsigned)hh < 64u && (unsigned)ww < 64u)
                s += mask[(hh * 2) * HW + ww * 2];
        }
    g_mm[i] = ((s * (1.0f / 9.0f)) == 0.0f) ? 1.0f : 0.0f;
}

// ---------------- Gram GEMM (FFMA2 packed fp32): G[b][i][j] = sum_c bd[c][i]*fd[c][j] ----------------
// M=N=4096, K=128. 128x128 block tile, 256 threads, 8x8 micro-tile, f32x2 packed.
__global__ __launch_bounds__(256) void k_gemm() {
    int bb = blockIdx.z;
    int i0 = blockIdx.y * 128;
    int j0 = blockIdx.x * 128;
    const float* A  = g_bd + (size_t)bb * C_ * L_;   // [c][i]
    const float* Bm = g_fd + (size_t)bb * C_ * L_;   // [c][j]
    __shared__ float As[16][128];
    __shared__ float Bs[16][128];

    u64 acc[8][4];
#pragma unroll
    for (int u = 0; u < 8; u++)
#pragma unroll
        for (int j = 0; j < 4; j++) acc[u][j] = 0ull;

    int tid = threadIdx.x;
    int tx = tid & 15, ty = tid >> 4;

    union U4 { float4 v; u64 u[2]; float f[4]; };

    for (int k0 = 0; k0 < 128; k0 += 16) {
#pragma unroll
        for (int x = tid; x < 512; x += 256) {       // 16 rows * 32 float4
            int kk = x >> 5, c4 = (x & 31) << 2;
            *(float4*)&As[kk][c4] = *(const float4*)&A[(size_t)(k0 + kk) * L_ + i0 + c4];
            *(float4*)&Bs[kk][c4] = *(const float4*)&Bm[(size_t)(k0 + kk) * L_ + j0 + c4];
        }
        __syncthreads();
#pragma unroll
        for (int k = 0; k < 16; k++) {
            U4 a0, a1, b0, b1;
            a0.v = *(float4*)&As[k][ty * 8];
            a1.v = *(float4*)&As[k][ty * 8 + 4];
            b0.v = *(float4*)&Bs[k][tx * 8];
            b1.v = *(float4*)&Bs[k][tx * 8 + 4];
            u64 bv[4] = {b0.u[0], b0.u[1], b1.u[0], b1.u[1]};
            float av[8] = {a0.f[0], a0.f[1], a0.f[2], a0.f[3],
                           a1.f[0], a1.f[1], a1.f[2], a1.f[3]};
#pragma unroll
            for (int u = 0; u < 8; u++) {
                u64 ad = pack_dup(av[u]);
#pragma unroll
                for (int j = 0; j < 4; j++) ffma2(acc[u][j], ad, bv[j]);
            }
        }
        __syncthreads();
    }
    float* Cp = g_bufA + ((size_t)bb << 24);
#pragma unroll
    for (int u = 0; u < 8; u++) {
        size_t ro = (size_t)(i0 + ty * 8 + u) * L_ + j0 + tx * 8;
        U4 o0, o1;
        o0.u[0] = acc[u][0]; o0.u[1] = acc[u][1];
        o1.u[0] = acc[u][2]; o1.u[1] = acc[u][3];
        *(float4*)&Cp[ro]     = o0.v;
        *(float4*)&Cp[ro + 4] = o1.v;
    }
}

// ---------------- combined dh+dw diagonal box-sum (9 taps) + patch norm ----------------
// Exact composition: dh-tap validity depends only on (hb,hf); dw-tap on (wb,wf);
// dw shifts never cross an hb boundary (validity enforced), so conditions decouple.
__global__ void k_combA() {
    size_t n = (size_t)blockIdx.x * blockDim.x + threadIdx.x;
    unsigned m = (unsigned)(n & (NMAT - 1));
    unsigned l = m >> 12, p = m & 4095;
    int hb = l >> 6, wb = l & 63, hf = p >> 6, wf = p & 63;
    const float* in = g_bufA;
    float v = 0.0f;
#pragma unroll
    for (int d1 = -1; d1 <= 1; d1++) {
        if ((unsigned)(hb + d1) >= 64u || (unsigned)(hf + d1) >= 64u) continue;
        long long base = (long long)n + (long long)d1 * 262208;   // 64*4097
#pragma unroll
        for (int d2 = -1; d2 <= 1; d2++) {
            if ((unsigned)(wb + d2) >= 64u || (unsigned)(wf + d2) >= 64u) continue;
            v += in[base + (long long)d2 * 4097];
        }
    }
    g_bufB[n] = v * g_norm[(n >> 24) * L_ + l];
}

// ---------------- combined fuse1 + fuse2 (transpose sandwich) + mask, output [p][l] ----------------
__global__ void k_combB() {
    int bz = blockIdx.z;
    int l0 = blockIdx.y << 5;
    int p0 = blockIdx.x << 5;
    __shared__ float s[32][33];
    int l = l0 + threadIdx.y;
    int p = p0 + threadIdx.x;
    int sl = ((l & 63) << 6) | (l >> 6);
    int sp = ((p & 63) << 6) | (p >> 6);
    const float* in = g_bufB + ((size_t)bz << 24);
    float v = 0.0f;
#pragma unroll
    for (int d4 = -1; d4 <= 1; d4++) {
        int xl = sl + d4, xp = sp + d4;
        if ((unsigned)xl >= 4096u || (unsigned)xp >= 4096u) continue;
        int l4 = ((xl & 63) << 6) | (xl >> 6);
        int p4 = ((xp & 63) << 6) | (xp >> 6);
#pragma unroll
        for (int d3 = -1; d3 <= 1; d3++) {
            int a = l4 + d3, c = p4 + d3;
            if ((unsigned)a < 4096u && (unsigned)c < 4096u)
                v += in[((size_t)a << 12) + c];
        }
    }
    s[threadIdx.y][threadIdx.x] = v * g_mm[l];
    __syncthreads();
    int po = p0 + threadIdx.y, lo = l0 + threadIdx.x;
    g_bufA[((size_t)bz << 24) + ((size_t)po << 12) + lo] = s[threadIdx.x][threadIdx.y];
}

// ---------------- softmax stats only: per-row max*SCALE and 1/sum(exp) ----------------
__global__ void k_stats() {
    int row = blockIdx.x;               // B_*L_ rows of [b][p][l]
    const float* r = g_bufA + (size_t)row * L_;
    __shared__ float red[256];
    int tid = threadIdx.x;

    float m = -3.4e38f;
    for (int i = tid; i < L_; i += 256) m = fmaxf(m, r[i]);
    red[tid] = m; __syncthreads();
    for (int s = 128; s > 0; s >>= 1) { if (tid < s) red[tid] = fmaxf(red[tid], red[tid + s]); __syncthreads(); }
    m = red[0] * SCALE_;
    __syncthreads();

    float sum = 0.0f;
    for (int i = tid; i < L_; i += 256) sum += expf(r[i] * SCALE_ - m);
    red[tid] = sum; __syncthreads();
    for (int s = 128; s > 0; s >>= 1) { if (tid < s) red[tid] += red[tid + s]; __syncthreads(); }
    if (tid == 0) { g_max[row] = m; g_inv[row] = 1.0f / red[0]; }
}

// ---------------- sparse transposed-conv paste (softmax reconstructed on the fly) ----------------
__global__ __launch_bounds__(512) void k_deconv(const float* __restrict__ bfull, float* __restrict__ out) {
    __shared__ int   s_idx[4096];
    __shared__ float s_w[4096];
    __shared__ int   s_cnt;
    int row = blockIdx.x;               // b*4096 + p
    int bb = row >> 12;
    int p  = row & 4095;
    int tid = threadIdx.x;
    if (tid == 0) s_cnt = 0;
    __syncthreads();

    const float* r = g_bufA + (size_t)row * L_;
    float mx = g_max[row], inv = g_inv[row];
    for (int i = tid; i < L_; i += 512) {
        float w = expf(r[i] * SCALE_ - mx) * inv * g_mm[i];
        if (w > TAU) { int k = atomicAdd(&s_cnt, 1); s_idx[k] = i; s_w[k] = w; }
    }
    __syncthreads();
    int n = s_cnt;

    int ih = p >> 6, iw = p & 63;
    int c  = tid >> 2, kw = tid & 3;
    int ow = 2 * iw - 1 + kw;
    if ((unsigned)ow >= (unsigned)HW) return;

    float*       obase = out   + ((size_t)(bb * C_ + c) * HW) * HW + ow;
    const float* bbase = bfull + ((size_t)(bb * C_ + c) * HW) * HW;

    for (int s2 = 0; s2 < n; s2++) {
        int l = s_idx[s2];
        float w = 0.25f * s_w[s2];
        int hb = l >> 6, wb = l & 63;
        int bc = 2 * wb - 1 + kw;
        if ((unsigned)bc >= (unsigned)HW) continue;
        const float* bp = bbase + bc;
#pragma unroll
        for (int kh = 0; kh < 4; kh++) {
            int oh = 2 * ih - 1 + kh;
            int br = 2 * hb - 1 + kh;
            if ((unsigned)oh < (unsigned)HW && (unsigned)br < (unsigned)HW) {
                atomicAdd(obase + oh * HW, w * bp[br * HW]);
            }
        }
    }
}

// ---------------- launcher ----------------
extern "C" void kernel_launch(void* const* d_in, const int* in_sizes, int n_in,
                              void* d_out, int out_size) {
    (void)in_sizes; (void)n_in;
    const float* f    = (const float*)d_in[0];
    const float* b    = (const float*)d_in[1];
    const float* mask = (const float*)d_in[2];
    float* out = (float*)d_out;

    k_zero<<<(out_size + 255) / 256, 256>>>(out, out_size);
    k_prep_ds<<<(B_ * C_ * L_) / 256, 256>>>(f, b);
    k_energy<<<(B_ * L_) / 256, 256>>>();
    k_norm<<<(B_ * L_) / 256, 256>>>();
    k_mm<<<L_ / 256, 256>>>(mask);

    dim3 gg(32, 32, B_);
    k_gemm<<<gg, 256>>>();

    int pblocks = (int)(((size_t)B_ * NMAT) / 256);   // 131072
    k_combA<<<pblocks, 256>>>();

    dim3 gt(128, 128, B_), bt(32, 32);
    k_combB<<<gt, bt>>>();

    k_stats<<<B_ * L_, 256>>>();
    k_deconv<<<B_ * L_, 512>>>(b, out);
}